// round 2
// baseline (speedup 1.0000x reference)
#include <cuda_runtime.h>

// Problem constants
#define NROWS    524288
#define NCH      30
#define BLK_ROWS 512
#define THREADS  512
#define NBLOCKS  (NROWS / BLK_ROWS)   // 1024

// FILTERS (6 x 30), compile-time constant from the reference
__constant__ float c_FILT[6 * 30] = {
    1,1,1,1,1,1,1,1,1,1,1,1,1,1,1,1,1,1,1,1,1,1,0,0,0,0,0,0,1,1,
    1,1,0,0,0,0,0,0,0,0,0,0,0,0,0,0,1,1,1,1,1,1,0,0,1,1,1,1,1,1,
    1,1,0,0,1,1,0,0,1,1,0,0,1,1,0,0,0,0,0,0,0,0,0,0,0,0,0,0,1,1,
    1,1,0,0,0,0,0,0,0,0,0,0,0,0,1,1,1,1,1,1,1,1,0,0,0,0,1,1,1,1,
    1,1,0,0,1,0,0,0,0,0,0,0,0,0,0,0,0,0,0,0,0,0,0,0,0,0,0,0,1,1,
    1,1,1,1,0,0,1,1,0,0,1,1,0,0,0,0,0,0,0,0,0,0,0,0,0,0,0,0,1,1
};

__global__ __launch_bounds__(THREADS, 3)
void ext_kernel(const float* __restrict__ tpl,   // (N,3)
                const float* __restrict__ cons,  // (N,8)
                const float* __restrict__ w_gas, // (8,30)
                const float* __restrict__ W1,    // (6,6,2)
                const float* __restrict__ b1,    // (6,6)
                const float* __restrict__ W2,    // (6,4,6)
                const float* __restrict__ b2,    // (6,4)
                const float* __restrict__ W3,    // (6,4,4)
                const float* __restrict__ b3,    // (6,4)
                const float* __restrict__ Wo,    // (6,4)
                const float* __restrict__ bo,    // (6,)
                float* __restrict__ out)         // (N,30,8)
{
    __shared__ float sW1[72], sb1[36], sW2[144], sb2[24];
    __shared__ float sW3[96], sb3[24], sWo[24], sbo[6];
    __shared__ __align__(16) float sTAB[240];           // TAB[ch*8 + j]
    __shared__ __align__(16) float sV[BLK_ROWS * 8];    // v[row][8]

    const int tid = threadIdx.x;
    const int n = blockIdx.x * BLK_ROWS + tid;

    // Prefetch per-row globals early (hides latency behind weight staging)
    const float  t0 = tpl[n * 3 + 0];
    const float  t1 = tpl[n * 3 + 1];
    const float4 c0 = __ldg(reinterpret_cast<const float4*>(cons) + n * 2 + 0);
    const float4 c1 = __ldg(reinterpret_cast<const float4*>(cons) + n * 2 + 1);

    // ---- stage weights + build TAB = exp(w_gas[j,ch]) * (j<2 ? 1 : FILT[j-2,ch]) ----
    if (tid < 144) sW2[tid] = W2[tid];
    if (tid < 96)  sW3[tid] = W3[tid];
    if (tid < 72)  sW1[tid] = W1[tid];
    if (tid < 36)  sb1[tid] = b1[tid];
    if (tid < 24)  { sb2[tid] = b2[tid]; sb3[tid] = b3[tid]; sWo[tid] = Wo[tid]; }
    if (tid < 6)   sbo[tid] = bo[tid];
    if (tid < 240) {
        int ch = tid >> 3, j = tid & 7;
        float e = __expf(w_gas[j * NCH + ch]);
        if (j >= 2) e *= c_FILT[(j - 2) * NCH + ch];
        sTAB[tid] = e;
    }
    __syncthreads();

    // ---- phase 1: one thread per row: tiny MLPs -> s[6], fold into v[8] ----
    {
        float s[6];
        #pragma unroll
        for (int g = 0; g < 6; g++) {
            float h1[6];
            #pragma unroll
            for (int h = 0; h < 6; h++) {
                float a = fmaf(sW1[g*12 + h*2 + 0], t0,
                          fmaf(sW1[g*12 + h*2 + 1], t1, sb1[g*6 + h]));
                h1[h] = fmaxf(a, 0.0f);
            }
            float h2[4];
            #pragma unroll
            for (int o = 0; o < 4; o++) {
                float a = sb2[g*4 + o];
                #pragma unroll
                for (int h = 0; h < 6; h++) a = fmaf(sW2[g*24 + o*6 + h], h1[h], a);
                h2[o] = fmaxf(a, 0.0f);
            }
            float h3[4];
            #pragma unroll
            for (int p = 0; p < 4; p++) {
                float a = sb3[g*4 + p];
                #pragma unroll
                for (int h = 0; h < 4; h++) a = fmaf(sW3[g*16 + p*4 + h], h2[h], a);
                h3[p] = fmaxf(a, 0.0f);
            }
            float z = sbo[g];
            #pragma unroll
            for (int p = 0; p < 4; p++) z = fmaf(sWo[g*4 + p], h3[p], z);
            s[g] = __fdividef(1.0f, 1.0f + __expf(-z));   // sigmoid
        }

        float4 v0 = make_float4(c0.x,         c0.y,         c0.z * s[0], c0.w * s[1]);
        float4 v1 = make_float4(c1.x * s[2],  c1.y * s[3],  c1.z * s[4], c1.w * s[5]);
        reinterpret_cast<float4*>(sV)[tid * 2 + 0] = v0;
        reinterpret_cast<float4*>(sV)[tid * 2 + 1] = v1;
    }
    __syncthreads();

    // ---- phase 2: 480 threads (15 warps) stream 512 rows x 60 float4, coalesced ----
    // float4 index within block = row*60 + rem;  rem -> (ch = rem>>1, j0 = (rem&1)*4)
    if (tid < 480) {
        const int rem = tid % 60;                 // fixed per thread
        const float4 tab = reinterpret_cast<const float4*>(sTAB)[rem];
        int voff = (tid / 60) * 2 + (rem & 1);    // float4 index into sV; +16 per iter
        const float4* V4 = reinterpret_cast<const float4*>(sV);
        float4* op = reinterpret_cast<float4*>(out)
                   + (size_t)blockIdx.x * (BLK_ROWS * 60) + tid;

        #pragma unroll 8
        for (int k = 0; k < BLK_ROWS / 8; k++) {  // 64 iterations
            float4 vv = V4[voff];
            float4 r;
            r.x = vv.x * tab.x;
            r.y = vv.y * tab.y;
            r.z = vv.z * tab.z;
            r.w = vv.w * tab.w;
            __stcs(op, r);   // streaming store: output never re-read
            voff += 16;      // 8 rows * 2 float4
            op   += 480;     // 480 float4 per pass
        }
    }
}

extern "C" void kernel_launch(void* const* d_in, const int* in_sizes, int n_in,
                              void* d_out, int out_size) {
    (void)in_sizes; (void)n_in; (void)out_size;
    ext_kernel<<<NBLOCKS, THREADS>>>(
        (const float*)d_in[0],  // tpl
        (const float*)d_in[1],  // cons
        (const float*)d_in[2],  // w_gas
        (const float*)d_in[3],  // ke_W1
        (const float*)d_in[4],  // ke_b1
        (const float*)d_in[5],  // ke_W2
        (const float*)d_in[6],  // ke_b2
        (const float*)d_in[7],  // ke_W3
        (const float*)d_in[8],  // ke_b3
        (const float*)d_in[9],  // ke_Wo
        (const float*)d_in[10], // ke_bo
        (float*)d_out);
}

// round 3
// speedup vs baseline: 1.0182x; 1.0182x over previous
#include <cuda_runtime.h>

// Problem constants
#define NROWS    524288
#define NCH      30
#define BLK_ROWS 256
#define THREADS  256
#define NBLOCKS  (NROWS / BLK_ROWS)   // 2048

// FILTERS (6 x 30), compile-time constant from the reference
__constant__ float c_FILT[6 * 30] = {
    1,1,1,1,1,1,1,1,1,1,1,1,1,1,1,1,1,1,1,1,1,1,0,0,0,0,0,0,1,1,
    1,1,0,0,0,0,0,0,0,0,0,0,0,0,0,0,1,1,1,1,1,1,0,0,1,1,1,1,1,1,
    1,1,0,0,1,1,0,0,1,1,0,0,1,1,0,0,0,0,0,0,0,0,0,0,0,0,0,0,1,1,
    1,1,0,0,0,0,0,0,0,0,0,0,0,0,1,1,1,1,1,1,1,1,0,0,0,0,1,1,1,1,
    1,1,0,0,1,0,0,0,0,0,0,0,0,0,0,0,0,0,0,0,0,0,0,0,0,0,0,0,1,1,
    1,1,1,1,0,0,1,1,0,0,1,1,0,0,0,0,0,0,0,0,0,0,0,0,0,0,0,0,1,1
};

__global__ __launch_bounds__(THREADS, 6)
void ext_kernel(const float* __restrict__ tpl,   // (N,3)
                const float* __restrict__ cons,  // (N,8)
                const float* __restrict__ w_gas, // (8,30)
                const float* __restrict__ W1,    // (6,6,2)
                const float* __restrict__ b1,    // (6,6)
                const float* __restrict__ W2,    // (6,4,6)
                const float* __restrict__ b2,    // (6,4)
                const float* __restrict__ W3,    // (6,4,4)
                const float* __restrict__ b3,    // (6,4)
                const float* __restrict__ Wo,    // (6,4)
                const float* __restrict__ bo,    // (6,)
                float* __restrict__ out)         // (N,30,8)
{
    __shared__ float sW1[72], sb1[36], sW2[144], sb2[24];
    __shared__ float sW3[96], sb3[24], sWo[24], sbo[6];
    __shared__ __align__(16) float sTAB[240];           // TAB[ch*8 + j]
    __shared__ __align__(16) float sV[BLK_ROWS * 8];    // v[row][8]

    const int tid = threadIdx.x;

    // ---- stage weights + build TAB = exp(w_gas[j,ch]) * (j<2 ? 1 : FILT[j-2,ch]) ----
    if (tid < 144) sW2[tid] = W2[tid];
    if (tid < 96)  sW3[tid] = W3[tid];
    if (tid < 72)  sW1[tid] = W1[tid];
    if (tid < 36)  sb1[tid] = b1[tid];
    if (tid < 24)  { sb2[tid] = b2[tid]; sb3[tid] = b3[tid]; sWo[tid] = Wo[tid]; }
    if (tid < 6)   sbo[tid] = bo[tid];
    if (tid < 240) {
        int ch = tid >> 3, j = tid & 7;
        float e = __expf(w_gas[j * NCH + ch]);
        if (j >= 2) e *= c_FILT[(j - 2) * NCH + ch];
        sTAB[tid] = e;
    }
    __syncthreads();

    // ---- phase 1: one thread per row: tiny MLPs -> s[6], fold into v[8] ----
    {
        const int n = blockIdx.x * BLK_ROWS + tid;
        const float t0 = tpl[n * 3 + 0];
        const float t1 = tpl[n * 3 + 1];
        const float4 c0 = reinterpret_cast<const float4*>(cons)[n * 2 + 0];
        const float4 c1 = reinterpret_cast<const float4*>(cons)[n * 2 + 1];

        float s[6];
        #pragma unroll
        for (int g = 0; g < 6; g++) {
            float h1[6];
            #pragma unroll
            for (int h = 0; h < 6; h++) {
                float a = fmaf(sW1[g*12 + h*2 + 0], t0,
                          fmaf(sW1[g*12 + h*2 + 1], t1, sb1[g*6 + h]));
                h1[h] = fmaxf(a, 0.0f);
            }
            float h2[4];
            #pragma unroll
            for (int o = 0; o < 4; o++) {
                float a = sb2[g*4 + o];
                #pragma unroll
                for (int h = 0; h < 6; h++) a = fmaf(sW2[g*24 + o*6 + h], h1[h], a);
                h2[o] = fmaxf(a, 0.0f);
            }
            float h3[4];
            #pragma unroll
            for (int p = 0; p < 4; p++) {
                float a = sb3[g*4 + p];
                #pragma unroll
                for (int h = 0; h < 4; h++) a = fmaf(sW3[g*16 + p*4 + h], h2[h], a);
                h3[p] = fmaxf(a, 0.0f);
            }
            float z = sbo[g];
            #pragma unroll
            for (int p = 0; p < 4; p++) z = fmaf(sWo[g*4 + p], h3[p], z);
            s[g] = __fdividef(1.0f, 1.0f + __expf(-z));   // sigmoid
        }

        float4 v0 = make_float4(c0.x,         c0.y,         c0.z * s[0], c0.w * s[1]);
        float4 v1 = make_float4(c1.x * s[2],  c1.y * s[3],  c1.z * s[4], c1.w * s[5]);
        reinterpret_cast<float4*>(sV)[tid * 2 + 0] = v0;
        reinterpret_cast<float4*>(sV)[tid * 2 + 1] = v1;
    }
    __syncthreads();

    // ---- phase 2: 240 threads stream 256 rows x 60 float4, coalesced ----
    // float4 index within block = row*60 + rem;  rem -> (ch = rem>>1, half = rem&1)
    if (tid < 240) {
        const int rem = tid % 60;                 // fixed per thread
        const float4 tab = reinterpret_cast<const float4*>(sTAB)[rem];
        int voff = (tid / 60) * 2 + (rem & 1);    // float4 index into sV; +8 per iter
        const float4* V4 = reinterpret_cast<const float4*>(sV);
        float4* op = reinterpret_cast<float4*>(out)
                   + (size_t)blockIdx.x * (BLK_ROWS * 60) + tid;

        #pragma unroll 4
        for (int k = 0; k < BLK_ROWS / 4; k++) {  // 64 iterations, 4 rows per pass
            float4 vv = V4[voff];
            float4 r;
            r.x = vv.x * tab.x;
            r.y = vv.y * tab.y;
            r.z = vv.z * tab.z;
            r.w = vv.w * tab.w;
            *op = r;
            voff += 8;       // 4 rows * 2 float4
            op   += 240;     // 240 float4 per pass
        }
    }
}

extern "C" void kernel_launch(void* const* d_in, const int* in_sizes, int n_in,
                              void* d_out, int out_size) {
    (void)in_sizes; (void)n_in; (void)out_size;
    ext_kernel<<<NBLOCKS, THREADS>>>(
        (const float*)d_in[0],  // tpl
        (const float*)d_in[1],  // cons
        (const float*)d_in[2],  // w_gas
        (const float*)d_in[3],  // ke_W1
        (const float*)d_in[4],  // ke_b1
        (const float*)d_in[5],  // ke_W2
        (const float*)d_in[6],  // ke_b2
        (const float*)d_in[7],  // ke_W3
        (const float*)d_in[8],  // ke_b3
        (const float*)d_in[9],  // ke_Wo
        (const float*)d_in[10], // ke_bo
        (float*)d_out);
}

// round 4
// speedup vs baseline: 1.0823x; 1.0630x over previous
#include <cuda_runtime.h>
#include <cstdint>

// Problem constants
#define NROWS      524288
#define NCH        30
#define BLK_ROWS   256
#define THREADS    256
#define NBLOCKS    (NROWS / BLK_ROWS)     // 2048
#define CHUNK_ROWS 16
#define CHUNK_F4   (CHUNK_ROWS * 60)      // 960 float4 = 15360 B
#define NCHUNKS    (BLK_ROWS / CHUNK_ROWS) // 16

// FILTERS (6 x 30), compile-time constant from the reference
__constant__ float c_FILT[6 * 30] = {
    1,1,1,1,1,1,1,1,1,1,1,1,1,1,1,1,1,1,1,1,1,1,0,0,0,0,0,0,1,1,
    1,1,0,0,0,0,0,0,0,0,0,0,0,0,0,0,1,1,1,1,1,1,0,0,1,1,1,1,1,1,
    1,1,0,0,1,1,0,0,1,1,0,0,1,1,0,0,0,0,0,0,0,0,0,0,0,0,0,0,1,1,
    1,1,0,0,0,0,0,0,0,0,0,0,0,0,1,1,1,1,1,1,1,1,0,0,0,0,1,1,1,1,
    1,1,0,0,1,0,0,0,0,0,0,0,0,0,0,0,0,0,0,0,0,0,0,0,0,0,0,0,1,1,
    1,1,1,1,0,0,1,1,0,0,1,1,0,0,0,0,0,0,0,0,0,0,0,0,0,0,0,0,1,1
};

__device__ __forceinline__ void bulk_store(void* gptr, uint32_t smem_addr, uint32_t bytes) {
    asm volatile(
        "cp.async.bulk.global.shared::cta.bulk_group [%0], [%1], %2;"
        :: "l"(gptr), "r"(smem_addr), "r"(bytes) : "memory");
}

__global__ __launch_bounds__(THREADS, 5)
void ext_kernel(const float* __restrict__ tpl,   // (N,3)
                const float* __restrict__ cons,  // (N,8)
                const float* __restrict__ w_gas, // (8,30)
                const float* __restrict__ W1,    // (6,6,2)
                const float* __restrict__ b1,    // (6,6)
                const float* __restrict__ W2,    // (6,4,6)
                const float* __restrict__ b2,    // (6,4)
                const float* __restrict__ W3,    // (6,4,4)
                const float* __restrict__ b3,    // (6,4)
                const float* __restrict__ Wo,    // (6,4)
                const float* __restrict__ bo,    // (6,)
                float* __restrict__ out)         // (N,30,8)
{
    __shared__ float sW1[72], sb1[36], sW2[144], sb2[24];
    __shared__ float sW3[96], sb3[24], sWo[24], sbo[6];
    __shared__ __align__(16) float sTAB[240];            // TAB[ch*8 + j]
    __shared__ __align__(16) float sV[BLK_ROWS * 8];     // v[row][8]
    __shared__ __align__(16) float sStage[2][CHUNK_F4 * 4]; // 2 x 15360 B staging

    const int tid = threadIdx.x;

    // ---- stage weights + build TAB = exp(w_gas[j,ch]) * (j<2 ? 1 : FILT[j-2,ch]) ----
    if (tid < 144) sW2[tid] = W2[tid];
    if (tid < 96)  sW3[tid] = W3[tid];
    if (tid < 72)  sW1[tid] = W1[tid];
    if (tid < 36)  sb1[tid] = b1[tid];
    if (tid < 24)  { sb2[tid] = b2[tid]; sb3[tid] = b3[tid]; sWo[tid] = Wo[tid]; }
    if (tid < 6)   sbo[tid] = bo[tid];
    if (tid < 240) {
        int ch = tid >> 3, j = tid & 7;
        float e = __expf(w_gas[j * NCH + ch]);
        if (j >= 2) e *= c_FILT[(j - 2) * NCH + ch];
        sTAB[tid] = e;
    }
    __syncthreads();

    // ---- phase 1: one thread per row: tiny MLPs -> s[6], fold into v[8] ----
    {
        const int n = blockIdx.x * BLK_ROWS + tid;
        const float t0 = tpl[n * 3 + 0];
        const float t1 = tpl[n * 3 + 1];
        const float4 c0 = reinterpret_cast<const float4*>(cons)[n * 2 + 0];
        const float4 c1 = reinterpret_cast<const float4*>(cons)[n * 2 + 1];

        float s[6];
        #pragma unroll
        for (int g = 0; g < 6; g++) {
            float h1[6];
            #pragma unroll
            for (int h = 0; h < 6; h++) {
                float a = fmaf(sW1[g*12 + h*2 + 0], t0,
                          fmaf(sW1[g*12 + h*2 + 1], t1, sb1[g*6 + h]));
                h1[h] = fmaxf(a, 0.0f);
            }
            float h2[4];
            #pragma unroll
            for (int o = 0; o < 4; o++) {
                float a = sb2[g*4 + o];
                #pragma unroll
                for (int h = 0; h < 6; h++) a = fmaf(sW2[g*24 + o*6 + h], h1[h], a);
                h2[o] = fmaxf(a, 0.0f);
            }
            float h3[4];
            #pragma unroll
            for (int p = 0; p < 4; p++) {
                float a = sb3[g*4 + p];
                #pragma unroll
                for (int h = 0; h < 4; h++) a = fmaf(sW3[g*16 + p*4 + h], h2[h], a);
                h3[p] = fmaxf(a, 0.0f);
            }
            float z = sbo[g];
            #pragma unroll
            for (int p = 0; p < 4; p++) z = fmaf(sWo[g*4 + p], h3[p], z);
            s[g] = __fdividef(1.0f, 1.0f + __expf(-z));   // sigmoid
        }

        float4 v0 = make_float4(c0.x,         c0.y,         c0.z * s[0], c0.w * s[1]);
        float4 v1 = make_float4(c1.x * s[2],  c1.y * s[3],  c1.z * s[4], c1.w * s[5]);
        reinterpret_cast<float4*>(sV)[tid * 2 + 0] = v0;
        reinterpret_cast<float4*>(sV)[tid * 2 + 1] = v1;
    }
    __syncthreads();

    // ---- phase 2: build 16-row chunks in SMEM, stream out via TMA bulk stores ----
    const int rem  = tid % 60;        // float4 lane within a row-pair layout
    const int rowg = tid / 60;        // 0..3 for tid<240
    const float4 tab = reinterpret_cast<const float4*>(sTAB)[rem];
    const float4* V4 = reinterpret_cast<const float4*>(sV);

    char* gbase = reinterpret_cast<char*>(out) + (size_t)blockIdx.x * (BLK_ROWS * 960);

    for (int k = 0; k < NCHUNKS; k++) {
        const int buf = k & 1;
        if (k >= 2) {
            if (tid == 0) {
                asm volatile("cp.async.bulk.wait_group.read 1;" ::: "memory");
            }
            __syncthreads();   // buffer 'buf' free for reuse
        }
        if (tid < 240) {
            float4* st = reinterpret_cast<float4*>(sStage[buf]);
            const int base = k * CHUNK_ROWS;
            #pragma unroll
            for (int i = 0; i < 4; i++) {
                const int row = rowg + 4 * i;          // 0..15
                float4 vv = V4[(base + row) * 2 + (rem & 1)];
                float4 r;
                r.x = vv.x * tab.x;
                r.y = vv.y * tab.y;
                r.z = vv.z * tab.z;
                r.w = vv.w * tab.w;
                st[row * 60 + rem] = r;
            }
        }
        __syncthreads();       // staging chunk complete
        if (tid == 0) {
            asm volatile("fence.proxy.async.shared::cta;" ::: "memory");
            uint32_t saddr = (uint32_t)__cvta_generic_to_shared(sStage[buf]);
            bulk_store(gbase + (size_t)k * (CHUNK_ROWS * 960), saddr, CHUNK_ROWS * 960);
            asm volatile("cp.async.bulk.commit_group;" ::: "memory");
        }
    }
    if (tid == 0) {
        asm volatile("cp.async.bulk.wait_group 0;" ::: "memory");
    }
}

extern "C" void kernel_launch(void* const* d_in, const int* in_sizes, int n_in,
                              void* d_out, int out_size) {
    (void)in_sizes; (void)n_in; (void)out_size;
    ext_kernel<<<NBLOCKS, THREADS>>>(
        (const float*)d_in[0],  // tpl
        (const float*)d_in[1],  // cons
        (const float*)d_in[2],  // w_gas
        (const float*)d_in[3],  // ke_W1
        (const float*)d_in[4],  // ke_b1
        (const float*)d_in[5],  // ke_W2
        (const float*)d_in[6],  // ke_b2
        (const float*)d_in[7],  // ke_W3
        (const float*)d_in[8],  // ke_b3
        (const float*)d_in[9],  // ke_Wo
        (const float*)d_in[10], // ke_bo
        (float*)d_out);
}